// round 13
// baseline (speedup 1.0000x reference)
#include <cuda_runtime.h>
#include <cuda_fp16.h>
#include <cstdint>

// Problem sizes (fixed).
#define NB  2048
#define DD  1024
#define HH  131072
#define CC  1024
#define SSZ 8192

// ---------------- scratch (device globals; no allocation allowed) -----------
__device__ __half g_Xh[NB * DD];               // X, fp16-rounded
__device__ __half g_Wgh[SSZ * DD];             // gathered W_hidden rows, fp16
__device__ float  g_bg[SSZ];                   // gathered b_hidden (exact fp32)
__device__ __half g_Woh[(size_t)CC * SSZ];     // gathered W_out cols, fp16
__device__ __half g_h[(size_t)NB * SSZ];       // relu hidden, fp16
__device__ int g_ids64;

#define DEVFN __device__ __forceinline__

DEVFN uint32_t smem_u32(const void* p) {
    uint32_t a;
    asm("{ .reg .u64 t; cvta.to.shared.u64 t, %1; cvt.u32.u64 %0, t; }"
        : "=r"(a) : "l"(p));
    return a;
}

DEVFN uint32_t pack2h(__half a, __half b) {
    return (uint32_t)__half_as_ushort(a) | ((uint32_t)__half_as_ushort(b) << 16);
}

// SW64 swizzle for 64-byte rows: XOR 16B-chunk bits [5:4] with row bits [8:7].
#define SWZ64(o) ((uint32_t)(o) ^ ((((uint32_t)(o)) >> 3) & 0x30u))

#define LDM4(r, addr) \
    asm volatile("ldmatrix.sync.aligned.m8n8.x4.shared.b16 {%0,%1,%2,%3}, [%4];" \
                 : "=r"((r)[0]), "=r"((r)[1]), "=r"((r)[2]), "=r"((r)[3]) \
                 : "r"(addr))

#define STS16(addr, v) \
    asm volatile("st.shared.v4.b32 [%0], {%1,%2,%3,%4};" \
                 :: "r"(addr), "r"((v).x), "r"((v).y), "r"((v).z), "r"((v).w))

DEVFN void mma16816(float* c, const uint32_t* a, uint32_t b0, uint32_t b1) {
    asm volatile(
        "mma.sync.aligned.m16n8k16.row.col.f32.f16.f16.f32 "
        "{%0,%1,%2,%3}, {%4,%5,%6,%7}, {%8,%9}, {%0,%1,%2,%3};"
        : "+f"(c[0]), "+f"(c[1]), "+f"(c[2]), "+f"(c[3])
        : "r"(a[0]), "r"(a[1]), "r"(a[2]), "r"(a[3]), "r"(b0), "r"(b1));
}

// ---------------- pre-pass kernels -------------------------------------------
__global__ void k_detect(const int* __restrict__ ids32) {
    if (threadIdx.x == 0) {
        int all0 = 1;
        for (int j = 1; j < 128; j += 2) all0 &= (ids32[j] == 0);
        g_ids64 = all0;
    }
}

DEVFN long long load_id(const void* idsp, int s) {
    return g_ids64 ? ((const long long*)idsp)[s] : (long long)((const int*)idsp)[s];
}

__global__ void k_cvtX(const float4* __restrict__ X4) {
    int i = blockIdx.x * blockDim.x + threadIdx.x;
    float4 v = X4[i];
    ((uint2*)g_Xh)[i] = make_uint2(
        pack2h(__float2half_rn(v.x), __float2half_rn(v.y)),
        pack2h(__float2half_rn(v.z), __float2half_rn(v.w)));
}

__global__ void k_gatherWh(const float* __restrict__ Wh, const float* __restrict__ bh,
                           const void* __restrict__ idsp) {
    int s = blockIdx.x;
    long long id = load_id(idsp, s);
    const float4* src = (const float4*)(Wh + (size_t)id * DD);
    uint2* dst = (uint2*)(g_Wgh + (size_t)s * DD);
    for (int j = threadIdx.x; j < DD / 4; j += blockDim.x) {
        float4 v = src[j];
        dst[j] = make_uint2(
            pack2h(__float2half_rn(v.x), __float2half_rn(v.y)),
            pack2h(__float2half_rn(v.z), __float2half_rn(v.w)));
    }
    if (threadIdx.x == 0) g_bg[s] = bh[id];
}

// Persistent column gather: 256 CTAs x 256 threads. Each thread owns ONE
// sample id (register-resident, no ids re-reads) and walks 128 c-rows with
// unroll-8 batches for MLP. Covers (c, s) exactly once:
//   s = (bx & 31) * 256 + tid;  c = (bx >> 5) + 8 * t, t = 0..127.
__global__ void __launch_bounds__(256) k_gatherWo(const float* __restrict__ Wo,
                                                  const void* __restrict__ idsp) {
    const int bx = blockIdx.x;
    const int tid = threadIdx.x;
    const int s = (bx & 31) * 256 + tid;
    const long long id = load_id(idsp, s);
    const float* src = Wo + id;
    __half* dst = g_Woh + s;
    const int c0 = bx >> 5;                    // 0..7
    #pragma unroll 1
    for (int j = 0; j < 128; j += 8) {
        float v[8];
        #pragma unroll
        for (int q = 0; q < 8; q++)
            v[q] = src[(size_t)(c0 + (j + q) * 8) * HH];
        #pragma unroll
        for (int q = 0; q < 8; q++)
            dst[(size_t)(c0 + (j + q) * 8) * SSZ] = __float2half_rn(v[q]);
    }
}

// ---------------- fp16 GEMM via mma.sync (m16n8k16) --------------------------
// C[M,N] = A[M,K]*B[N,K]^T, fp32 data pre-rounded to fp16 (rn). One MMA term:
// fp16 mantissa (11 bits) == tf32 mantissa, but k16 shape halves instructions.
// CTA tile 128 x TN, BK=32 halfs (64B rows), SW64 swizzle, double buffer,
// LDG.128 -> register -> STS.128 pipelined fill, 8 warps (4m x 2n),
// ldmatrix.x4 both operands (K-major). 2 CTAs/SM.
// EPI==0: +bias, relu -> outH fp16. EPI==1: +bias -> outF fp32.

template <int TN, int EPI>
__global__ void __launch_bounds__(256, 2) k_gemm(
    const __half* __restrict__ A, const __half* __restrict__ B,
    const float* __restrict__ bias,
    float* __restrict__ outF, __half* __restrict__ outH,
    int K, int ldo)
{
    constexpr int NJ  = TN / 32;                // x4 B-loads per kstep (n16 each)
    constexpr int NF  = TN / 16;                // n8 accum frags per warp
    constexpr int NCB = TN / 64;                // B 16B-chunks per thread
    constexpr uint32_t ASZ = 128 * 64;          // 8 KB A tile (128 rows x 64B)
    constexpr uint32_t BSZ = (uint32_t)TN * 64;
    constexpr uint32_t STG = ASZ + BSZ;

    extern __shared__ char dsm[];
    __shared__ float s_bias[TN];

    const int tid = threadIdx.x;
    const int wid = tid >> 5, lane = tid & 31;
    const int m0 = blockIdx.y * 128;
    const int n0 = blockIdx.x * TN;
    const uint32_t sbase = (smem_u32(dsm) + 1023u) & ~1023u;

    for (int j = tid; j < TN; j += 256) s_bias[j] = bias[n0 + j];

    // ---- fill descriptors: chunk c -> row c>>2, 16B-word c&3 (coalesced) ----
    uint32_t asoff[2];
    const __half* pA[2];
    #pragma unroll
    for (int j = 0; j < 2; j++) {
        int c = tid + j * 256, row = c >> 2, wi = c & 3;
        asoff[j] = SWZ64(row * 64 + wi * 16);
        pA[j] = A + (size_t)(m0 + row) * K + wi * 8;
    }
    uint32_t bsoff[NCB];
    const __half* pB[NCB];
    #pragma unroll
    for (int j = 0; j < NCB; j++) {
        int c = tid + j * 256, row = c >> 2, wi = c & 3;
        bsoff[j] = SWZ64(row * 64 + wi * 16);
        pB[j] = B + (size_t)(n0 + row) * K + wi * 8;
    }

    // ---- ldmatrix offsets (loop-invariant, swizzled) ----
    const int wm = wid >> 1, wn = wid & 1;
    const int rA = wm * 32 + (lane & 15);
    const int rB = wn * (TN / 2) + (lane & 15);
    const int kb = (lane >> 4) * 16;
    uint32_t aoff[2][2], boff[NJ][2];
    #pragma unroll
    for (int mi = 0; mi < 2; mi++)
        #pragma unroll
        for (int ks = 0; ks < 2; ks++)
            aoff[mi][ks] = SWZ64((rA + mi * 16) * 64 + ks * 32 + kb);
    #pragma unroll
    for (int nj = 0; nj < NJ; nj++)
        #pragma unroll
        for (int ks = 0; ks < 2; ks++)
            boff[nj][ks] = SWZ64((rB + nj * 16) * 64 + ks * 32 + kb);

    float acc[2][NF][4];
    #pragma unroll
    for (int i = 0; i < 2; i++)
        #pragma unroll
        for (int j = 0; j < NF; j++)
            #pragma unroll
            for (int q = 0; q < 4; q++) acc[i][j][q] = 0.0f;

    uint4 sA[2], sB[NCB];

    auto ldg = [&](int kt) {
        const size_t off = (size_t)kt * 32;     // BK = 32 halfs
        #pragma unroll
        for (int j = 0; j < 2; j++) sA[j] = *(const uint4*)(pA[j] + off);
        #pragma unroll
        for (int j = 0; j < NCB; j++) sB[j] = *(const uint4*)(pB[j] + off);
    };
    auto sts = [&](int b) {
        const uint32_t s0 = sbase + (uint32_t)b * STG;
        #pragma unroll
        for (int j = 0; j < 2; j++) STS16(s0 + asoff[j], sA[j]);
        #pragma unroll
        for (int j = 0; j < NCB; j++) STS16(s0 + ASZ + bsoff[j], sB[j]);
    };

    const int KT = K >> 5;
    ldg(0);
    sts(0);
    __syncthreads();

    for (int kt = 0; kt < KT; kt++) {
        const bool more = (kt + 1 < KT);
        if (more) ldg(kt + 1);                  // LDG overlapped with mma below

        const uint32_t s0 = sbase + (uint32_t)(kt & 1) * STG;
        const uint32_t tA = s0, tB = s0 + ASZ;

        #pragma unroll
        for (int ks = 0; ks < 2; ks++) {        // k16 per kstep
            uint32_t a[2][4];
            #pragma unroll
            for (int mi = 0; mi < 2; mi++) LDM4(a[mi], tA + aoff[mi][ks]);
            #pragma unroll
            for (int nj = 0; nj < NJ; nj++) {
                uint32_t bb[4];                 // r0/r1 = b0 of n8-frag 0/1, r2/r3 = b1
                LDM4(bb, tB + boff[nj][ks]);
                #pragma unroll
                for (int mi = 0; mi < 2; mi++) {
                    #pragma unroll
                    for (int p = 0; p < 2; p++)
                        mma16816(acc[mi][nj * 2 + p], a[mi], bb[p], bb[p + 2]);
                }
            }
        }
        if (more) sts((kt + 1) & 1);
        __syncthreads();
    }

    // ---- epilogue: c0,c1 -> row lane>>2, cols 2(lane&3)+{0,1}; c2,c3 -> +8 ----
    const int er = lane >> 2;
    const int ec = 2 * (lane & 3);
    #pragma unroll
    for (int mi = 0; mi < 2; mi++) {
        const int row = m0 + wm * 32 + mi * 16 + er;
        #pragma unroll
        for (int nf = 0; nf < NF; nf++) {
            const int colL = wn * (TN / 2) + nf * 8 + ec;
            const size_t o0 = (size_t)row * ldo + (size_t)(n0 + colL);
            const size_t o1 = o0 + (size_t)8 * ldo;
            float v0 = acc[mi][nf][0] + s_bias[colL];
            float v1 = acc[mi][nf][1] + s_bias[colL + 1];
            float v2 = acc[mi][nf][2] + s_bias[colL];
            float v3 = acc[mi][nf][3] + s_bias[colL + 1];
            if constexpr (EPI == 0) {
                *(uint32_t*)(outH + o0) = pack2h(
                    __float2half_rn(fmaxf(v0, 0.0f)), __float2half_rn(fmaxf(v1, 0.0f)));
                *(uint32_t*)(outH + o1) = pack2h(
                    __float2half_rn(fmaxf(v2, 0.0f)), __float2half_rn(fmaxf(v3, 0.0f)));
            } else {
                *(float2*)(outF + o0) = make_float2(v0, v1);
                *(float2*)(outF + o1) = make_float2(v2, v3);
            }
        }
    }
}

// ---------------- launch -----------------------------------------------------
// Fork-join: persistent gatherWo on a high-priority side stream; joins before
// GEMM2. Host stream/events created once (no device allocation).
extern "C" void kernel_launch(void* const* d_in, const int* in_sizes, int n_in,
                              void* d_out, int out_size) {
    const float* X   = (const float*)d_in[0];
    const float* Wh  = (const float*)d_in[1];
    const float* bh  = (const float*)d_in[2];
    const float* Wo  = (const float*)d_in[3];
    const float* bo  = (const float*)d_in[4];
    const void*  ids = d_in[5];
    float* out = (float*)d_out;
    (void)in_sizes; (void)n_in; (void)out_size;

    static cudaStream_t s2 = nullptr;
    static cudaEvent_t evFork = nullptr, evJoin = nullptr;
    if (s2 == nullptr) {
        int lo, hi;
        cudaDeviceGetStreamPriorityRange(&lo, &hi);
        cudaStreamCreateWithPriority(&s2, cudaStreamNonBlocking, hi);
        cudaEventCreateWithFlags(&evFork, cudaEventDisableTiming);
        cudaEventCreateWithFlags(&evJoin, cudaEventDisableTiming);
    }

    void *pXh, *pWgh, *pbg, *pWoh, *ph;
    cudaGetSymbolAddress(&pXh, g_Xh);
    cudaGetSymbolAddress(&pWgh, g_Wgh);
    cudaGetSymbolAddress(&pbg, g_bg);
    cudaGetSymbolAddress(&pWoh, g_Woh);
    cudaGetSymbolAddress(&ph, g_h);

    // smem: 2 stages; stage = 8KB (A) + TN*64B (B). +1KB alignment pad.
    const int smem1 = 2 * (8192 + 128 * 64) + 1024;  // 33792
    const int smem2 = 2 * (8192 + 64 * 64) + 1024;   // 25600
    cudaFuncSetAttribute(k_gemm<128, 0>, cudaFuncAttributeMaxDynamicSharedMemorySize, smem1);
    cudaFuncSetAttribute(k_gemm<64, 1>,  cudaFuncAttributeMaxDynamicSharedMemorySize, smem2);

    k_detect<<<1, 32>>>((const int*)ids);

    // Fork: side stream waits for k_detect, then persistent column gather.
    cudaEventRecord(evFork, 0);
    cudaStreamWaitEvent(s2, evFork, 0);
    k_gatherWo<<<256, 256, 0, s2>>>(Wo, ids);
    cudaEventRecord(evJoin, s2);

    // Main branch: GEMM1 prerequisites + GEMM1.
    k_cvtX<<<(NB * DD / 4) / 256, 256>>>((const float4*)X);
    k_gatherWh<<<SSZ, 128>>>(Wh, bh, ids);

    // GEMM1: h = fp16(relu(X * Wg^T + bg)). M=2048, N=8192, K=1024.
    k_gemm<128, 0><<<dim3(SSZ / 128, NB / 128), 256, smem1>>>(
        (const __half*)pXh, (const __half*)pWgh, (const float*)pbg,
        nullptr, (__half*)ph, DD, SSZ);

    // Join: GEMM2 needs both h (main branch) and Woh (side branch).
    cudaStreamWaitEvent(0, evJoin, 0);

    // GEMM2: out = h * WoT^T + b_out (fp32). M=2048, N=1024, K=8192.
    k_gemm<64, 1><<<dim3(CC / 64, NB / 128), 256, smem2>>>(
        (const __half*)ph, (const __half*)pWoh, bo,
        out, nullptr, SSZ, CC);
}

// round 14
// speedup vs baseline: 1.0199x; 1.0199x over previous
#include <cuda_runtime.h>
#include <cuda_fp16.h>
#include <cstdint>

// Problem sizes (fixed).
#define NB  2048
#define DD  1024
#define HH  131072
#define CC  1024
#define SSZ 8192

// ---------------- scratch (device globals; no allocation allowed) -----------
__device__ __half g_Xh[NB * DD];               // X, fp16-rounded
__device__ __half g_Wgh[SSZ * DD];             // gathered W_hidden rows, fp16
__device__ float  g_bg[SSZ];                   // gathered b_hidden (exact fp32)
__device__ __half g_Woh[(size_t)CC * SSZ];     // gathered W_out cols, fp16
__device__ __half g_h[(size_t)NB * SSZ];       // relu hidden, fp16
__device__ int g_ids64;

#define DEVFN __device__ __forceinline__

DEVFN uint32_t smem_u32(const void* p) {
    uint32_t a;
    asm("{ .reg .u64 t; cvta.to.shared.u64 t, %1; cvt.u32.u64 %0, t; }"
        : "=r"(a) : "l"(p));
    return a;
}

DEVFN uint32_t pack2h(__half a, __half b) {
    return (uint32_t)__half_as_ushort(a) | ((uint32_t)__half_as_ushort(b) << 16);
}

// SW64 swizzle for 64-byte rows: XOR 16B-chunk bits [5:4] with row bits [8:7].
#define SWZ64(o) ((uint32_t)(o) ^ ((((uint32_t)(o)) >> 3) & 0x30u))

#define LDM4(r, addr) \
    asm volatile("ldmatrix.sync.aligned.m8n8.x4.shared.b16 {%0,%1,%2,%3}, [%4];" \
                 : "=r"((r)[0]), "=r"((r)[1]), "=r"((r)[2]), "=r"((r)[3]) \
                 : "r"(addr))

#define STS16(addr, v) \
    asm volatile("st.shared.v4.b32 [%0], {%1,%2,%3,%4};" \
                 :: "r"(addr), "r"((v).x), "r"((v).y), "r"((v).z), "r"((v).w))

DEVFN void mma16816(float* c, const uint32_t* a, uint32_t b0, uint32_t b1) {
    asm volatile(
        "mma.sync.aligned.m16n8k16.row.col.f32.f16.f16.f32 "
        "{%0,%1,%2,%3}, {%4,%5,%6,%7}, {%8,%9}, {%0,%1,%2,%3};"
        : "+f"(c[0]), "+f"(c[1]), "+f"(c[2]), "+f"(c[3])
        : "r"(a[0]), "r"(a[1]), "r"(a[2]), "r"(a[3]), "r"(b0), "r"(b1));
}

// ---------------- pre-pass kernels -------------------------------------------
__global__ void k_detect(const int* __restrict__ ids32) {
    if (threadIdx.x == 0) {
        int all0 = 1;
        for (int j = 1; j < 128; j += 2) all0 &= (ids32[j] == 0);
        g_ids64 = all0;
    }
}

DEVFN long long load_id(const void* idsp, int s) {
    return g_ids64 ? ((const long long*)idsp)[s] : (long long)((const int*)idsp)[s];
}

__global__ void k_cvtX(const float4* __restrict__ X4) {
    int i = blockIdx.x * blockDim.x + threadIdx.x;
    float4 v = X4[i];
    ((uint2*)g_Xh)[i] = make_uint2(
        pack2h(__float2half_rn(v.x), __float2half_rn(v.y)),
        pack2h(__float2half_rn(v.z), __float2half_rn(v.w)));
}

__global__ void k_gatherWh(const float* __restrict__ Wh, const float* __restrict__ bh,
                           const void* __restrict__ idsp) {
    int s = blockIdx.x;
    long long id = load_id(idsp, s);
    const float4* src = (const float4*)(Wh + (size_t)id * DD);
    uint2* dst = (uint2*)(g_Wgh + (size_t)s * DD);
    for (int j = threadIdx.x; j < DD / 4; j += blockDim.x) {
        float4 v = src[j];
        dst[j] = make_uint2(
            pack2h(__float2half_rn(v.x), __float2half_rn(v.y)),
            pack2h(__float2half_rn(v.z), __float2half_rn(v.w)));
    }
    if (threadIdx.x == 0) g_bg[s] = bh[id];
}

// Column gather (R12 grid version — at the DRAM floor; keep per-c locality).
__global__ void __launch_bounds__(256) k_gatherWo(const float* __restrict__ Wo,
                                                  const void* __restrict__ idsp) {
    int s = blockIdx.x * blockDim.x + threadIdx.x;
    int c = blockIdx.y;
    long long id = load_id(idsp, s);
    g_Woh[(size_t)c * SSZ + s] = __float2half_rn(Wo[(size_t)c * HH + (size_t)id]);
}

// ---------------- fp16 GEMM via mma.sync (m16n8k16) --------------------------
// C[M,N] = A[M,K]*B[N,K]^T, fp32 data pre-rounded to fp16 (rn). One MMA term.
// CTA tile 128 x TN, BK=32 halfs (64B rows), SW64 swizzle, double buffer,
// LDG.128 -> register -> STS.128 pipelined fill, 8 warps (4m x 2n),
// ldmatrix.x4 both operands (K-major). 2 CTAs/SM. TN=64 keeps regs < 128 so
// gather CTAs can co-reside on the same SMs (RF headroom).
// EPI==0: +bias, relu -> outH fp16. EPI==1: +bias -> outF fp32.

template <int TN, int EPI>
__global__ void __launch_bounds__(256, 2) k_gemm(
    const __half* __restrict__ A, const __half* __restrict__ B,
    const float* __restrict__ bias,
    float* __restrict__ outF, __half* __restrict__ outH,
    int K, int ldo)
{
    constexpr int NJ  = TN / 32;                // x4 B-loads per kstep (n16 each)
    constexpr int NF  = TN / 16;                // n8 accum frags per warp
    constexpr int NCB = TN / 64;                // B 16B-chunks per thread
    constexpr uint32_t ASZ = 128 * 64;          // 8 KB A tile (128 rows x 64B)
    constexpr uint32_t BSZ = (uint32_t)TN * 64;
    constexpr uint32_t STG = ASZ + BSZ;

    extern __shared__ char dsm[];
    __shared__ float s_bias[TN];

    const int tid = threadIdx.x;
    const int wid = tid >> 5, lane = tid & 31;
    const int m0 = blockIdx.y * 128;
    const int n0 = blockIdx.x * TN;
    const uint32_t sbase = (smem_u32(dsm) + 1023u) & ~1023u;

    for (int j = tid; j < TN; j += 256) s_bias[j] = bias[n0 + j];

    // ---- fill descriptors: chunk c -> row c>>2, 16B-word c&3 (coalesced) ----
    uint32_t asoff[2];
    const __half* pA[2];
    #pragma unroll
    for (int j = 0; j < 2; j++) {
        int c = tid + j * 256, row = c >> 2, wi = c & 3;
        asoff[j] = SWZ64(row * 64 + wi * 16);
        pA[j] = A + (size_t)(m0 + row) * K + wi * 8;
    }
    uint32_t bsoff[NCB];
    const __half* pB[NCB];
    #pragma unroll
    for (int j = 0; j < NCB; j++) {
        int c = tid + j * 256, row = c >> 2, wi = c & 3;
        bsoff[j] = SWZ64(row * 64 + wi * 16);
        pB[j] = B + (size_t)(n0 + row) * K + wi * 8;
    }

    // ---- ldmatrix offsets (loop-invariant, swizzled) ----
    const int wm = wid >> 1, wn = wid & 1;
    const int rA = wm * 32 + (lane & 15);
    const int rB = wn * (TN / 2) + (lane & 15);
    const int kb = (lane >> 4) * 16;
    uint32_t aoff[2][2], boff[NJ][2];
    #pragma unroll
    for (int mi = 0; mi < 2; mi++)
        #pragma unroll
        for (int ks = 0; ks < 2; ks++)
            aoff[mi][ks] = SWZ64((rA + mi * 16) * 64 + ks * 32 + kb);
    #pragma unroll
    for (int nj = 0; nj < NJ; nj++)
        #pragma unroll
        for (int ks = 0; ks < 2; ks++)
            boff[nj][ks] = SWZ64((rB + nj * 16) * 64 + ks * 32 + kb);

    float acc[2][NF][4];
    #pragma unroll
    for (int i = 0; i < 2; i++)
        #pragma unroll
        for (int j = 0; j < NF; j++)
            #pragma unroll
            for (int q = 0; q < 4; q++) acc[i][j][q] = 0.0f;

    uint4 sA[2], sB[NCB];

    auto ldg = [&](int kt) {
        const size_t off = (size_t)kt * 32;     // BK = 32 halfs
        #pragma unroll
        for (int j = 0; j < 2; j++) sA[j] = *(const uint4*)(pA[j] + off);
        #pragma unroll
        for (int j = 0; j < NCB; j++) sB[j] = *(const uint4*)(pB[j] + off);
    };
    auto sts = [&](int b) {
        const uint32_t s0 = sbase + (uint32_t)b * STG;
        #pragma unroll
        for (int j = 0; j < 2; j++) STS16(s0 + asoff[j], sA[j]);
        #pragma unroll
        for (int j = 0; j < NCB; j++) STS16(s0 + ASZ + bsoff[j], sB[j]);
    };

    const int KT = K >> 5;
    ldg(0);
    sts(0);
    __syncthreads();

    for (int kt = 0; kt < KT; kt++) {
        const bool more = (kt + 1 < KT);
        if (more) ldg(kt + 1);                  // LDG overlapped with mma below

        const uint32_t s0 = sbase + (uint32_t)(kt & 1) * STG;
        const uint32_t tA = s0, tB = s0 + ASZ;

        #pragma unroll
        for (int ks = 0; ks < 2; ks++) {        // k16 per kstep
            uint32_t a[2][4];
            #pragma unroll
            for (int mi = 0; mi < 2; mi++) LDM4(a[mi], tA + aoff[mi][ks]);
            #pragma unroll
            for (int nj = 0; nj < NJ; nj++) {
                uint32_t bb[4];                 // r0/r1 = b0 of n8-frag 0/1, r2/r3 = b1
                LDM4(bb, tB + boff[nj][ks]);
                #pragma unroll
                for (int mi = 0; mi < 2; mi++) {
                    #pragma unroll
                    for (int p = 0; p < 2; p++)
                        mma16816(acc[mi][nj * 2 + p], a[mi], bb[p], bb[p + 2]);
                }
            }
        }
        if (more) sts((kt + 1) & 1);
        __syncthreads();
    }

    // ---- epilogue: c0,c1 -> row lane>>2, cols 2(lane&3)+{0,1}; c2,c3 -> +8 ----
    const int er = lane >> 2;
    const int ec = 2 * (lane & 3);
    #pragma unroll
    for (int mi = 0; mi < 2; mi++) {
        const int row = m0 + wm * 32 + mi * 16 + er;
        #pragma unroll
        for (int nf = 0; nf < NF; nf++) {
            const int colL = wn * (TN / 2) + nf * 8 + ec;
            const size_t o0 = (size_t)row * ldo + (size_t)(n0 + colL);
            const size_t o1 = o0 + (size_t)8 * ldo;
            float v0 = acc[mi][nf][0] + s_bias[colL];
            float v1 = acc[mi][nf][1] + s_bias[colL + 1];
            float v2 = acc[mi][nf][2] + s_bias[colL];
            float v3 = acc[mi][nf][3] + s_bias[colL + 1];
            if constexpr (EPI == 0) {
                *(uint32_t*)(outH + o0) = pack2h(
                    __float2half_rn(fmaxf(v0, 0.0f)), __float2half_rn(fmaxf(v1, 0.0f)));
                *(uint32_t*)(outH + o1) = pack2h(
                    __float2half_rn(fmaxf(v2, 0.0f)), __float2half_rn(fmaxf(v3, 0.0f)));
            } else {
                *(float2*)(outF + o0) = make_float2(v0, v1);
                *(float2*)(outF + o1) = make_float2(v2, v3);
            }
        }
    }
}

// ---------------- launch -----------------------------------------------------
// Fork-join: gatherWo on a high-priority side stream overlaps GEMM1 (TN=64
// leaves ~16K free regs/SM so gather CTAs can co-reside). Joins before GEMM2.
extern "C" void kernel_launch(void* const* d_in, const int* in_sizes, int n_in,
                              void* d_out, int out_size) {
    const float* X   = (const float*)d_in[0];
    const float* Wh  = (const float*)d_in[1];
    const float* bh  = (const float*)d_in[2];
    const float* Wo  = (const float*)d_in[3];
    const float* bo  = (const float*)d_in[4];
    const void*  ids = d_in[5];
    float* out = (float*)d_out;
    (void)in_sizes; (void)n_in; (void)out_size;

    static cudaStream_t s2 = nullptr;
    static cudaEvent_t evFork = nullptr, evJoin = nullptr;
    if (s2 == nullptr) {
        int lo, hi;
        cudaDeviceGetStreamPriorityRange(&lo, &hi);
        cudaStreamCreateWithPriority(&s2, cudaStreamNonBlocking, hi);
        cudaEventCreateWithFlags(&evFork, cudaEventDisableTiming);
        cudaEventCreateWithFlags(&evJoin, cudaEventDisableTiming);
    }

    void *pXh, *pWgh, *pbg, *pWoh, *ph;
    cudaGetSymbolAddress(&pXh, g_Xh);
    cudaGetSymbolAddress(&pWgh, g_Wgh);
    cudaGetSymbolAddress(&pbg, g_bg);
    cudaGetSymbolAddress(&pWoh, g_Woh);
    cudaGetSymbolAddress(&ph, g_h);

    // smem: 2 stages; stage = 8KB (A) + 64*64B (B). +1KB alignment pad.
    const int smem64 = 2 * (8192 + 64 * 64) + 1024;   // 25600
    cudaFuncSetAttribute(k_gemm<64, 0>, cudaFuncAttributeMaxDynamicSharedMemorySize, smem64);
    cudaFuncSetAttribute(k_gemm<64, 1>, cudaFuncAttributeMaxDynamicSharedMemorySize, smem64);

    k_detect<<<1, 32>>>((const int*)ids);

    // Fork: side stream waits for k_detect, then column gather (DRAM-bound).
    cudaEventRecord(evFork, 0);
    cudaStreamWaitEvent(s2, evFork, 0);
    k_gatherWo<<<dim3(SSZ / 256, CC), 256, 0, s2>>>(Wo, ids);
    cudaEventRecord(evJoin, s2);

    // Main branch: GEMM1 prerequisites + GEMM1 (tensor-bound; overlaps gather).
    k_cvtX<<<(NB * DD / 4) / 256, 256>>>((const float4*)X);
    k_gatherWh<<<SSZ, 128>>>(Wh, bh, ids);

    // GEMM1: h = fp16(relu(X * Wg^T + bg)). M=2048, N=8192, K=1024. TN=64.
    k_gemm<64, 0><<<dim3(SSZ / 64, NB / 128), 256, smem64>>>(
        (const __half*)pXh, (const __half*)pWgh, (const float*)pbg,
        nullptr, (__half*)ph, DD, SSZ);

    // Join: GEMM2 needs both h (main branch) and Woh (side branch).
    cudaStreamWaitEvent(0, evJoin, 0);

    // GEMM2: out = h * WoT^T + b_out (fp32). M=2048, N=1024, K=8192.
    k_gemm<64, 1><<<dim3(CC / 64, NB / 128), 256, smem64>>>(
        (const __half*)ph, (const __half*)pWoh, bo,
        out, nullptr, SSZ, CC);
}